// round 17
// baseline (speedup 1.0000x reference)
#include <cuda_runtime.h>
#include <cuda_bf16.h>
#include <math_constants.h>
#include <cstdint>

// Problem constants
constexpr int Bb  = 2;
constexpr int Ss  = 2048;
constexpr int Dd  = 1024;
constexpr int Hh  = 16;
constexpr int DKk = 64;
constexpr int MM  = Bb * Ss;      // 4096

// tf32-rounded fp32 operands
__device__ float g_xt[MM * Dd];
__device__ float g_wt[4 * Dd * Dd];    // Q,K,V,O order
__device__ float g_of[MM * Dd];        // FA output (tf32-rounded)
// bf16 hi/lo Q/K/V for flash attention
__device__ __nv_bfloat16 g_qhi[MM * Dd];
__device__ __nv_bfloat16 g_qlo[MM * Dd];
__device__ __nv_bfloat16 g_khi[MM * Dd];
__device__ __nv_bfloat16 g_klo[MM * Dd];
__device__ __nv_bfloat16 g_vhi[MM * Dd];
__device__ __nv_bfloat16 g_vlo[MM * Dd];
// RoPE cos/sin table: [s][j] -> (cos, sin)
__device__ float2 g_csn[Ss * 32];

// ---------------------------------------------------------------------------
// Helpers
// ---------------------------------------------------------------------------
__device__ __forceinline__ uint32_t smem_u32(const void* p) {
    uint32_t a;
    asm("{ .reg .u64 t; cvta.to.shared.u64 t, %1; cvt.u32.u64 %0, t; }"
        : "=r"(a) : "l"(p));
    return a;
}
__device__ __forceinline__ float to_tf32(float x) {
    float y;
    asm("cvt.rna.tf32.f32 %0, %1;" : "=f"(y) : "f"(x));
    return y;
}
__device__ __forceinline__ uint32_t lds32(uint32_t a) {
    uint32_t v;
    asm volatile("ld.shared.b32 %0, [%1];" : "=r"(v) : "r"(a));
    return v;
}
__device__ __forceinline__ void mma16808(float* c, const uint32_t* a, const uint32_t* b) {
    asm volatile(
        "mma.sync.aligned.m16n8k8.row.col.f32.tf32.tf32.f32 "
        "{%0,%1,%2,%3}, {%4,%5,%6,%7}, {%8,%9}, {%0,%1,%2,%3};"
        : "+f"(c[0]), "+f"(c[1]), "+f"(c[2]), "+f"(c[3])
        : "r"(a[0]), "r"(a[1]), "r"(a[2]), "r"(a[3]), "r"(b[0]), "r"(b[1]));
}
__device__ __forceinline__ void mma16816(float* c, const uint32_t* a, const uint32_t* b) {
    asm volatile(
        "mma.sync.aligned.m16n8k16.row.col.f32.bf16.bf16.f32 "
        "{%0,%1,%2,%3}, {%4,%5,%6,%7}, {%8,%9}, {%0,%1,%2,%3};"
        : "+f"(c[0]), "+f"(c[1]), "+f"(c[2]), "+f"(c[3])
        : "r"(a[0]), "r"(a[1]), "r"(a[2]), "r"(a[3]), "r"(b[0]), "r"(b[1]));
}
__device__ __forceinline__ void ldsm4(uint32_t* r, uint32_t a) {
    asm volatile("ldmatrix.sync.aligned.m8n8.x4.shared.b16 {%0,%1,%2,%3}, [%4];"
        : "=r"(r[0]), "=r"(r[1]), "=r"(r[2]), "=r"(r[3]) : "r"(a));
}
__device__ __forceinline__ void ldsm4t(uint32_t* r, uint32_t a) {
    asm volatile("ldmatrix.sync.aligned.m8n8.x4.trans.shared.b16 {%0,%1,%2,%3}, [%4];"
        : "=r"(r[0]), "=r"(r[1]), "=r"(r[2]), "=r"(r[3]) : "r"(a));
}
__device__ __forceinline__ void cp_async16(uint32_t dst, const void* src) {
    asm volatile("cp.async.cg.shared.global [%0], [%1], 16;" :: "r"(dst), "l"(src) : "memory");
}
__device__ __forceinline__ void cp_commit() { asm volatile("cp.async.commit_group;" ::: "memory"); }
__device__ __forceinline__ void cp_wait1()  { asm volatile("cp.async.wait_group 1;" ::: "memory"); }
__device__ __forceinline__ void cp_wait0()  { asm volatile("cp.async.wait_group 0;" ::: "memory"); }
__device__ __forceinline__ float ex2(float x) {
    float y;
    asm("ex2.approx.ftz.f32 %0, %1;" : "=f"(y) : "f"(x));
    return y;
}
__device__ __forceinline__ uint32_t pack_bf16(float lo, float hi) {
    uint32_t r;
    asm("cvt.rn.bf16x2.f32 %0, %1, %2;" : "=r"(r) : "f"(hi), "f"(lo));
    return r;
}

// ---------------------------------------------------------------------------
// Single-pass TF32 GEMM core: acc = A[M,K]*B[N,K]^T
// 128x64 CTA tile, BK=32, 8 warps (32x32 warp tile), cp.async double buffer.
// 3 CTAs/SM (regs <= 85 via launch_bounds) for latency hiding.
// smem rows padded to 144 B (36 floats) -> conflict-free lds.32 frag loads.
// ---------------------------------------------------------------------------
constexpr int TF_AMAT  = 128 * 144;          // 18432 B  (A: 128 rows)
constexpr int TF_BMAT  = 64 * 144;           //  9216 B  (B: 64 rows)
constexpr int TF_STG   = TF_AMAT + TF_BMAT;  // 27648 B per stage
constexpr int TF_SMEM  = 2 * TF_STG;         // 55296 B

__device__ __forceinline__ void tf32_gemm_core(
    const float* __restrict__ A, const float* __restrict__ B,
    int K, float acc[2][4][4])
{
    extern __shared__ char smem[];
    const uint32_t sb = smem_u32(smem);

    const int tid = threadIdx.x;
    const int wid = tid >> 5;
    const int lid = tid & 31;
    const int bm  = blockIdx.y * 128;
    const int bn  = blockIdx.x * 64;
    const int wm  = wid >> 1;          // 0..3 -> M offset wm*32
    const int wn  = wid & 1;           // 0..1 -> N offset wn*32
    const int lg  = lid >> 2;          // group 0..7
    const int lt  = lid & 3;           // thread-in-group

    const int nIter = K / 32;

    auto load_chunk = [&](int c, int s) {
        const int koff = c * 32;
        const uint32_t st = sb + (uint32_t)s * TF_STG;
        #pragma unroll
        for (int i = tid; i < 1536; i += 256) {
            if (i < 1024) {                       // A: 128 rows x 32 floats
                const int r = i >> 3;
                const int q = i & 7;
                cp_async16(st + (uint32_t)(r * 144 + q * 16),
                           A + (size_t)(bm + r) * K + koff + q * 4);
            } else {                              // B: 64 rows x 32 floats
                const int j = i - 1024;
                const int r = j >> 3;
                const int q = j & 7;
                cp_async16(st + (uint32_t)(TF_AMAT + r * 144 + q * 16),
                           B + (size_t)(bn + r) * K + koff + q * 4);
            }
        }
        cp_commit();
    };

    load_chunk(0, 0);
    load_chunk(1, 1);

    for (int c = 0; c < nIter; c++) {
        if (c + 2 < nIter) cp_wait1(); else cp_wait0();
        __syncthreads();

        const uint32_t st = sb + (uint32_t)(c & 1) * TF_STG;
        const uint32_t sA = st;
        const uint32_t sB = st + TF_AMAT;

        #pragma unroll
        for (int k8 = 0; k8 < 32; k8 += 8) {
            uint32_t af[2][4], bf[4][2];
            #pragma unroll
            for (int mt = 0; mt < 2; mt++) {
                const uint32_t base = sA + (uint32_t)((wm * 32 + mt * 16 + lg) * 144
                                                      + (k8 + lt) * 4);
                af[mt][0] = lds32(base);
                af[mt][1] = lds32(base + 8 * 144);
                af[mt][2] = lds32(base + 16);
                af[mt][3] = lds32(base + 8 * 144 + 16);
            }
            #pragma unroll
            for (int nt = 0; nt < 4; nt++) {
                const uint32_t base = sB + (uint32_t)((wn * 32 + nt * 8 + lg) * 144
                                                      + (k8 + lt) * 4);
                bf[nt][0] = lds32(base);
                bf[nt][1] = lds32(base + 16);
            }
            #pragma unroll
            for (int mt = 0; mt < 2; mt++)
                #pragma unroll
                for (int nt = 0; nt < 4; nt++)
                    mma16808(acc[mt][nt], af[mt], bf[nt]);
        }
        __syncthreads();
        if (c + 2 < nIter) load_chunk(c + 2, c & 1);
    }
}

// Out-projection: tf32 GEMM, plain fp32 store to d_out
__global__ void __launch_bounds__(256, 3)
tf_gemm(const float* __restrict__ A, const float* __restrict__ B,
        float* __restrict__ C, int N, int K)
{
    float acc[2][4][4] = {};
    tf32_gemm_core(A, B, K, acc);

    const int tid = threadIdx.x;
    const int wid = tid >> 5;
    const int lid = tid & 31;
    const int bm  = blockIdx.y * 128;
    const int bn  = blockIdx.x * 64;
    const int wm  = wid >> 1;
    const int wn  = wid & 1;
    const int cr  = lid >> 2;
    const int cc  = (lid & 3) * 2;
    #pragma unroll
    for (int mt = 0; mt < 2; mt++) {
        #pragma unroll
        for (int nt = 0; nt < 4; nt++) {
            const int row = bm + wm * 32 + mt * 16 + cr;
            const int col = bn + wn * 32 + nt * 8 + cc;
            float2 v0 = {acc[mt][nt][0], acc[mt][nt][1]};
            float2 v1 = {acc[mt][nt][2], acc[mt][nt][3]};
            *(float2*)&C[(size_t)row * N + col]       = v0;
            *(float2*)&C[(size_t)(row + 8) * N + col] = v1;
        }
    }
}

// Fused QKV projection (tf32): z=0 Q (rope+scale+split), z=1 K (rope+split), z=2 V (split)
__global__ void __launch_bounds__(256, 3)
tf_gemm_qkv(const float* __restrict__ xt, const float* __restrict__ wt,
            __nv_bfloat16* __restrict__ qhi, __nv_bfloat16* __restrict__ qlo,
            __nv_bfloat16* __restrict__ khi, __nv_bfloat16* __restrict__ klo,
            __nv_bfloat16* __restrict__ vhi, __nv_bfloat16* __restrict__ vlo)
{
    const int z = blockIdx.z;
    const float* B = wt + (size_t)z * Dd * Dd;

    float acc[2][4][4] = {};
    tf32_gemm_core(xt, B, Dd, acc);

    __nv_bfloat16* dhi = (z == 0) ? qhi : (z == 1) ? khi : vhi;
    __nv_bfloat16* dlo = (z == 0) ? qlo : (z == 1) ? klo : vlo;
    const float scale = (z == 0) ? 0.18033688011112042f : 1.0f;  // 0.125*log2(e)

    const int tid = threadIdx.x;
    const int wid = tid >> 5;
    const int lid = tid & 31;
    const int bm  = blockIdx.y * 128;
    const int bn  = blockIdx.x * 64;
    const int wm  = wid >> 1;
    const int wn  = wid & 1;
    const int cr  = lid >> 2;
    const int cc  = (lid & 3) * 2;

    #pragma unroll
    for (int mt = 0; mt < 2; mt++) {
        #pragma unroll
        for (int nt = 0; nt < 4; nt++) {
            const int row0 = bm + wm * 32 + mt * 16 + cr;
            const int col  = bn + wn * 32 + nt * 8 + cc;   // even -> rope pair
            float a0 = acc[mt][nt][0], a1 = acc[mt][nt][1];
            float b0 = acc[mt][nt][2], b1 = acc[mt][nt][3];
            if (z < 2) {
                const int j = (col & 63) >> 1;
                const float2 cs0 = g_csn[(row0 & (Ss - 1)) * 32 + j];
                const float2 cs1 = g_csn[((row0 + 8) & (Ss - 1)) * 32 + j];
                float t0 = cs0.x * a0 - cs0.y * a1;
                float t1 = cs0.y * a0 + cs0.x * a1;
                a0 = t0 * scale; a1 = t1 * scale;
                t0 = cs1.x * b0 - cs1.y * b1;
                t1 = cs1.y * b0 + cs1.x * b1;
                b0 = t0 * scale; b1 = t1 * scale;
            }
            {
                const uint32_t hb = pack_bf16(a0, a1);
                const uint32_t lb = pack_bf16(a0 - __uint_as_float(hb << 16),
                                              a1 - __uint_as_float(hb & 0xFFFF0000u));
                const size_t idx = (size_t)row0 * Dd + col;
                *(uint32_t*)&dhi[idx] = hb;
                *(uint32_t*)&dlo[idx] = lb;
            }
            {
                const uint32_t hb = pack_bf16(b0, b1);
                const uint32_t lb = pack_bf16(b0 - __uint_as_float(hb << 16),
                                              b1 - __uint_as_float(hb & 0xFFFF0000u));
                const size_t idx = (size_t)(row0 + 8) * Dd + col;
                *(uint32_t*)&dhi[idx] = hb;
                *(uint32_t*)&dlo[idx] = lb;
            }
        }
    }
}

// ---------------------------------------------------------------------------
// Prep kernels: round fp32 -> tf32 (rna). Unbiased, error ~2^-12.
// ---------------------------------------------------------------------------
__global__ void prep_x(const float* __restrict__ src, float* __restrict__ dst, int n4)
{
    int i = blockIdx.x * blockDim.x + threadIdx.x;
    if (i >= n4) return;
    float4 x = ((const float4*)src)[i];
    float4 y = { to_tf32(x.x), to_tf32(x.y), to_tf32(x.z), to_tf32(x.w) };
    ((float4*)dst)[i] = y;
}

__global__ void prep_w4(const float* __restrict__ w0, const float* __restrict__ w1,
                        const float* __restrict__ w2, const float* __restrict__ w3,
                        float* __restrict__ dst)
{
    const int z = blockIdx.z;
    const float* src = (z == 0) ? w0 : (z == 1) ? w1 : (z == 2) ? w2 : w3;
    const int n4 = Dd * Dd / 4;
    int i = blockIdx.x * blockDim.x + threadIdx.x;
    if (i >= n4) return;
    float4 x = ((const float4*)src)[i];
    float4 y = { to_tf32(x.x), to_tf32(x.y), to_tf32(x.z), to_tf32(x.w) };
    ((float4*)(dst + (size_t)z * Dd * Dd))[i] = y;
}

// RoPE cos/sin table from token positions
__global__ void rope_cs(const int* __restrict__ pos)
{
    int idx = blockIdx.x * blockDim.x + threadIdx.x;
    if (idx >= Ss * 32) return;
    const int s = idx >> 5;
    const int j = idx & 31;
    const float p    = (float)pos[s];
    const float freq = exp2f((float)j * (-2.0f / 64.0f) * 13.28771237954945f);
    float sn, cs;
    sincosf(p * freq, &sn, &cs);
    g_csn[idx] = make_float2(cs, sn);
}

// ---------------------------------------------------------------------------
// Tensor-core causal flash attention (unchanged)
// ---------------------------------------------------------------------------
constexpr int FA_LD   = 72;
constexpr int FA_MATB = 64 * FA_LD * 2;
constexpr int FA_STG  = 4 * FA_MATB;
constexpr int FA_SMEM = 2 * FA_STG;

__global__ void __launch_bounds__(256)
fa_mma(const __nv_bfloat16* __restrict__ qhi, const __nv_bfloat16* __restrict__ qlo,
       const __nv_bfloat16* __restrict__ khi, const __nv_bfloat16* __restrict__ klo,
       const __nv_bfloat16* __restrict__ vhi, const __nv_bfloat16* __restrict__ vlo,
       float* __restrict__ of)
{
    extern __shared__ char smem[];
    const uint32_t sb = smem_u32(smem);

    const int tid = threadIdx.x;
    const int wid = tid >> 5;
    const int lid = tid & 31;
    const int bh  = blockIdx.y;
    const int b   = bh >> 4;
    const int h   = bh & (Hh - 1);
    const int q0  = blockIdx.x * 128;
    const size_t gbase = (size_t)(b * Ss) * Dd + h * DKk;

    const int ri = lid & 7;
    const int g  = lid >> 3;
    const int ag_r = ((g & 1) << 3) + ri;
    const int ag_c = (g >> 1) << 3;
    const int bg_r = ((g >> 1) << 3) + ri;
    const int bg_c = (g & 1) << 3;
    const int tr_r = lid & 15;
    const int tr_c = (lid >> 4) << 3;

    #pragma unroll
    for (int i = tid; i < 2048; i += 256) {
        const int mat = i >> 10;
        const int r   = (i >> 3) & 127;
        const int c8  = (i & 7) * 8;
        const __nv_bfloat16* src = (mat ? qlo : qhi) + gbase + (size_t)(q0 + r) * Dd + c8;
        cp_async16(sb + (uint32_t)mat * (128 * 144) + r * 144 + c8 * 2, src);
    }
    cp_commit();
    cp_wait0();
    __syncthreads();

    uint32_t qh[4][4], ql[4][4];
    #pragma unroll
    for (int kt = 0; kt < 4; kt++) {
        const uint32_t off = (uint32_t)((wid * 16 + ag_r) * 144 + (kt * 16 + ag_c) * 2);
        ldsm4(qh[kt], sb + off);
        ldsm4(ql[kt], sb + 128 * 144 + off);
    }
    __syncthreads();

    float o[8][4] = {};
    float m0 = -1e30f, m1 = -1e30f, l0 = 0.f, l1 = 0.f;

    const int ntile = q0 / 64 + 2;

    auto loadKV = [&](int t, int s) {
        const int k0 = t * 64;
        const uint32_t st = sb + (uint32_t)s * FA_STG;
        #pragma unroll
        for (int i = tid; i < 2048; i += 256) {
            const int mat = i >> 9;
            const int r   = (i >> 3) & 63;
            const int c8  = (i & 7) * 8;
            const __nv_bfloat16* gp =
                (mat == 0 ? khi : mat == 1 ? klo : mat == 2 ? vhi : vlo)
                + gbase + (size_t)(k0 + r) * Dd + c8;
            cp_async16(st + (uint32_t)mat * FA_MATB + r * 144 + c8 * 2, gp);
        }
        cp_commit();
    };

    loadKV(0, 0);
    loadKV(1, 1);

    for (int t = 0; t < ntile; t++) {
        if (t + 2 < ntile) cp_wait1(); else cp_wait0();
        __syncthreads();

        const int k0 = t * 64;
        const uint32_t st = sb + (uint32_t)(t & 1) * FA_STG;

        if (k0 <= q0 + wid * 16 + 15) {
            float s[8][4] = {};

            #pragma unroll
            for (int kt = 0; kt < 4; kt++) {
                uint32_t kh[4][4], kl[4][4];
                #pragma unroll
                for (int np = 0; np < 4; np++) {
                    const uint32_t off = (uint32_t)((np * 16 + bg_r) * 144
                                                    + (kt * 16 + bg_c) * 2);
                    ldsm4(kh[np], st + off);
                    ldsm4(kl[np], st + FA_MATB + off);
                }
                #pragma unroll
                for (int np = 0; np < 4; np++) {
                    mma16816(s[2 * np],     qh[kt], &kh[np][0]);
                    mma16816(s[2 * np],     qh[kt], &kl[np][0]);
                    mma16816(s[2 * np],     ql[kt], &kh[np][0]);
                    mma16816(s[2 * np + 1], qh[kt], &kh[np][2]);
                    mma16816(s[2 * np + 1], qh[kt], &kl[np][2]);
                    mma16816(s[2 * np + 1], ql[kt], &kh[np][2]);
                }
            }

            if (k0 + 63 > q0 + wid * 16) {
                const int qr0 = q0 + wid * 16 + (lid >> 2);
                #pragma unroll
                for (int nt = 0; nt < 8; nt++) {
                    #pragma unroll
                    for (int j = 0; j < 4; j++) {
                        const int kc = k0 + nt * 8 + (lid & 3) * 2 + (j & 1);
                        const int qr = qr0 + ((j >> 1) << 3);
                        if (kc > qr) s[nt][j] = -1e30f;
                    }
                }
            }

            float mx0 = -1e30f, mx1 = -1e30f;
            #pragma unroll
            for (int nt = 0; nt < 8; nt++) {
                mx0 = fmaxf(mx0, fmaxf(s[nt][0], s[nt][1]));
                mx1 = fmaxf(mx1, fmaxf(s[nt][2], s[nt][3]));
            }
            mx0 = fmaxf(mx0, __shfl_xor_sync(0xFFFFFFFFu, mx0, 1));
            mx0 = fmaxf(mx0, __shfl_xor_sync(0xFFFFFFFFu, mx0, 2));
            mx1 = fmaxf(mx1, __shfl_xor_sync(0xFFFFFFFFu, mx1, 1));
            mx1 = fmaxf(mx1, __shfl_xor_sync(0xFFFFFFFFu, mx1, 2));

            const float mn0 = fmaxf(m0, mx0);
            const float mn1 = fmaxf(m1, mx1);
            const float c0 = ex2(m0 - mn0);
            const float c1 = ex2(m1 - mn1);
            m0 = mn0; m1 = mn1;

            float sum0 = 0.f, sum1 = 0.f;
            #pragma unroll
            for (int nt = 0; nt < 8; nt++) {
                s[nt][0] = ex2(s[nt][0] - mn0);
                s[nt][1] = ex2(s[nt][1] - mn0);
                s[nt][2] = ex2(s[nt][2] - mn1);
                s[nt][3] = ex2(s[nt][3] - mn1);
                sum0 += s[nt][0] + s[nt][1];
                sum1 += s[nt][2] + s[nt][3];
            }
            sum0 += __shfl_xor_sync(0xFFFFFFFFu, sum0, 1);
            sum0 += __shfl_xor_sync(0xFFFFFFFFu, sum0, 2);
            sum1 += __shfl_xor_sync(0xFFFFFFFFu, sum1, 1);
            sum1 += __shfl_xor_sync(0xFFFFFFFFu, sum1, 2);
            l0 = l0 * c0 + sum0;
            l1 = l1 * c1 + sum1;

            #pragma unroll
            for (int nt = 0; nt < 8; nt++) {
                o[nt][0] *= c0; o[nt][1] *= c0;
                o[nt][2] *= c1; o[nt][3] *= c1;
            }

            #pragma unroll
            for (int kt = 0; kt < 4; kt++) {
                uint32_t ph[4], pl[4];
                #pragma unroll
                for (int half = 0; half < 2; half++) {
                    const float* sp = s[2 * kt + half];
                    const uint32_t hA = pack_bf16(sp[0], sp[1]);
                    const uint32_t hB = pack_bf16(sp[2], sp[3]);
                    const float lA0 = sp[0] - __uint_as_float(hA << 16);
                    const float lA1 = sp[1] - __uint_as_float(hA & 0xFFFF0000u);
                    const float lB0 = sp[2] - __uint_as_float(hB << 16);
                    const float lB1 = sp[3] - __uint_as_float(hB & 0xFFFF0000u);
                    ph[2 * half]     = hA;
                    ph[2 * half + 1] = hB;
                    pl[2 * half]     = pack_bf16(lA0, lA1);
                    pl[2 * half + 1] = pack_bf16(lB0, lB1);
                }
                uint32_t pA[4] = {ph[0], ph[1], ph[2], ph[3]};
                uint32_t pB[4] = {pl[0], pl[1], pl[2], pl[3]};

                uint32_t vh[4][4], vl[4][4];
                #pragma unroll
                for (int nn = 0; nn < 4; nn++) {
                    const uint32_t off = (uint32_t)((kt * 16 + tr_r) * 144
                                                    + (nn * 16 + tr_c) * 2);
                    ldsm4t(vh[nn], st + 2 * FA_MATB + off);
                    ldsm4t(vl[nn], st + 3 * FA_MATB + off);
                }
                #pragma unroll
                for (int nn = 0; nn < 4; nn++) {
                    mma16816(o[2 * nn],     pA, &vh[nn][0]);
                    mma16816(o[2 * nn],     pA, &vl[nn][0]);
                    mma16816(o[2 * nn],     pB, &vh[nn][0]);
                    mma16816(o[2 * nn + 1], pA, &vh[nn][2]);
                    mma16816(o[2 * nn + 1], pA, &vl[nn][2]);
                    mma16816(o[2 * nn + 1], pB, &vh[nn][2]);
                }
            }
        }

        __syncthreads();
        if (t + 2 < ntile) loadKV(t + 2, t & 1);
    }

    // epilogue: normalize, round to tf32, store fp32
    const float i0 = 1.f / l0;
    const float i1 = 1.f / l1;
    const int r0 = q0 + wid * 16 + (lid >> 2);
    const int cb = (lid & 3) * 2;
    #pragma unroll
    for (int nt = 0; nt < 8; nt++) {
        const int col = h * DKk + nt * 8 + cb;
        {
            float2 v = { to_tf32(o[nt][0] * i0), to_tf32(o[nt][1] * i0) };
            *(float2*)&of[(size_t)(b * Ss + r0) * Dd + col] = v;
        }
        {
            float2 v = { to_tf32(o[nt][2] * i1), to_tf32(o[nt][3] * i1) };
            *(float2*)&of[(size_t)(b * Ss + r0 + 8) * Dd + col] = v;
        }
    }
}

// ---------------------------------------------------------------------------
// Launch
// ---------------------------------------------------------------------------
extern "C" void kernel_launch(void* const* d_in, const int* in_sizes, int n_in,
                              void* d_out, int out_size)
{
    const float* x   = (const float*)d_in[0];
    const int*   pos = (const int*)  d_in[1];
    const float* WQ  = (const float*)d_in[2];
    const float* WK  = (const float*)d_in[3];
    const float* WV  = (const float*)d_in[4];
    const float* WO  = (const float*)d_in[5];
    float* out = (float*)d_out;

    float *xt, *wt, *of;
    __nv_bfloat16 *qhi, *qlo, *khi, *klo, *vhi, *vlo;
    cudaGetSymbolAddress((void**)&xt, g_xt);
    cudaGetSymbolAddress((void**)&wt, g_wt);
    cudaGetSymbolAddress((void**)&of, g_of);
    cudaGetSymbolAddress((void**)&qhi, g_qhi);
    cudaGetSymbolAddress((void**)&qlo, g_qlo);
    cudaGetSymbolAddress((void**)&khi, g_khi);
    cudaGetSymbolAddress((void**)&klo, g_klo);
    cudaGetSymbolAddress((void**)&vhi, g_vhi);
    cudaGetSymbolAddress((void**)&vlo, g_vlo);

    cudaFuncSetAttribute(tf_gemm,     cudaFuncAttributeMaxDynamicSharedMemorySize, TF_SMEM);
    cudaFuncSetAttribute(tf_gemm_qkv, cudaFuncAttributeMaxDynamicSharedMemorySize, TF_SMEM);
    cudaFuncSetAttribute(fa_mma,      cudaFuncAttributeMaxDynamicSharedMemorySize, FA_SMEM);

    // 1. round x to tf32
    prep_x<<<(MM * Dd / 4 + 255) / 256, 256>>>(x, xt, MM * Dd / 4);
    // 2. round weights to tf32 (one launch, z=4)
    {
        dim3 grid((Dd * Dd / 4 + 255) / 256, 1, 4);
        prep_w4<<<grid, 256>>>(WQ, WK, WV, WO, wt);
    }
    // 3. RoPE cos/sin table
    rope_cs<<<(Ss * 32 + 255) / 256, 256>>>(pos);
    // 4. fused QKV projection (tf32, 128x64 tiles) + RoPE + bf16 split
    {
        dim3 grid(Dd / 64, MM / 128, 3);
        tf_gemm_qkv<<<grid, 256, TF_SMEM>>>(xt, wt, qhi, qlo, khi, klo, vhi, vlo);
    }
    // 5. tensor-core flash attention (unchanged)
    {
        dim3 fgrid(Ss / 128, Bb * Hh);
        fa_mma<<<fgrid, 256, FA_SMEM>>>(qhi, qlo, khi, klo, vhi, vlo, of);
    }
    // 6. output projection (tf32, 128x64 tiles)
    {
        dim3 grid(Dd / 64, MM / 128);
        tf_gemm<<<grid, 256, TF_SMEM>>>(of, wt + 3 * (size_t)Dd * Dd, out, Dd, Dd);
    }
}